// round 3
// baseline (speedup 1.0000x reference)
#include <cuda_runtime.h>
#include <math.h>
#include <float.h>

#define B 64
#define C 32
#define HH 16
#define WW 16
#define VOCAB 4096
#define NPIX (B*HH*WW)          // 16384
#define NELEM (NPIX*C)          // 524288

// ---------------- device scratch (static, no allocations) ----------------
__device__ float  g_frest[NELEM];          // residual, BHWC
__device__ float  g_fhat [NELEM];          // accumulator, BHWC
__device__ float  g_tmp  [64*13*16*32];    // pooling intermediate [b,p,w,c]
__device__ float  g_z    [64*13*13*32];    // pooled z, largest non-last scale (pn=13)
__device__ float2 g_part [16384];          // partial (score, idx) per (chunk, vec)
__device__ int    g_idx  [NPIX];           // argmin indices, largest scale
__device__ float  g_esq  [VOCAB];          // ||e_j||^2 (reference rounding order)
__device__ int    g_upi  [9][16];          // cubic tap start index per (scale, out-pos)
__device__ float  g_upw  [9][16][4];       // cubic tap weights  per (scale, out-pos)

__device__ __constant__ int d_PNS[10] = {1,2,3,4,5,6,8,10,13,16};

// Keys cubic kernel (a = -0.5), matching jax _fill_keys_cubic_kernel, fp32 ops
__device__ __forceinline__ float keys_cubic(float x) {
    if (x >= 2.f) return 0.f;
    if (x >= 1.f) return ((-0.5f*x + 2.5f)*x - 4.f)*x + 2.f;
    return ((1.5f*x - 2.5f)*x)*x + 1.f;
}

// ---------------- init: bicubic upsample tap tables ----------------
// sample_f = (o+0.5)*(pn/16) - 0.5 ; pn/16 is exact in fp32. 4-tap window,
// weights normalized by in-range sum (jax compute_weight_mat).
__global__ void k_init_weights() {
    int t = threadIdx.x;
    if (t < 9*16) {
        int si = t >> 4, o = t & 15;
        int pn = d_PNS[si];
        float inv_scale = (float)pn / 16.0f;               // exact
        float sf = ((float)o + 0.5f) * inv_scale - 0.5f;
        int i0 = (int)floorf(sf) - 1;
        float w[4]; float s = 0.f;
        #pragma unroll
        for (int a = 0; a < 4; a++) {
            int i = i0 + a;
            float wv = 0.f;
            if (i >= 0 && i < pn) wv = keys_cubic(fabsf(sf - (float)i));
            w[a] = wv; s += wv;
        }
        float inv = (fabsf(s) > 1000.f * 1.1920929e-07f) ? 1.f / s : 0.f;
        g_upi[si][o] = i0;
        #pragma unroll
        for (int a = 0; a < 4; a++) g_upw[si][o][a] = w[a] * inv;
    }
}

// ---------------- ||e_j||^2 : rounded squares, sequential ascending adds ----------------
__global__ void k_esq(const float* __restrict__ emb) {
    int j = blockIdx.x * blockDim.x + threadIdx.x;
    if (j < VOCAB) {
        const float4* e4 = (const float4*)(emb + (size_t)j * C);
        float s = 0.f;
        #pragma unroll
        for (int k = 0; k < 8; k++) {
            float4 v = e4[k];
            s = __fadd_rn(s, __fmul_rn(v.x, v.x));
            s = __fadd_rn(s, __fmul_rn(v.y, v.y));
            s = __fadd_rn(s, __fmul_rn(v.z, v.z));
            s = __fadd_rn(s, __fmul_rn(v.w, v.w));
        }
        g_esq[j] = s;
    }
}

// ---------------- init: BCHW -> BHWC transpose, f_hat = 0 ----------------
__global__ void k_init(const float* __restrict__ f) {
    int t = blockIdx.x * blockDim.x + threadIdx.x;
    if (t < NELEM) {
        int c = t & 31; int w = (t >> 5) & 15; int h = (t >> 9) & 15; int b = t >> 13;
        g_frest[t] = f[((b*C + c)*HH + h)*WW + w];
        g_fhat[t]  = 0.f;
    }
}

// ---------------- area pool stage 1: contract H (einsum contracts h first) ----------------
// tmp[b,p,w,c] = sum_h fma(Mh[p,h], f_rest[b,h,w,c]) ascending h (zero terms are exact no-ops)
__global__ void k_pool_h(int pn, int total /* = B*pn*16*32 */) {
    int t = blockIdx.x * blockDim.x + threadIdx.x;
    if (t >= total) return;
    int c = t & 31; int w = (t >> 5) & 15; int pb = t >> 9;
    int p = pb % pn; int b = pb / pn;
    int s = (p*HH)/pn, e = ((p+1)*HH + pn - 1)/pn;
    float wh = 1.0f / (float)(e - s);
    float acc = 0.f;
    for (int h = s; h < e; h++)
        acc = fmaf(wh, g_frest[((b*HH + h)*WW + w)*C + c], acc);
    g_tmp[t] = acc;
}

// ---------------- area pool stage 2: contract W ----------------
// z[b,p,q,c] = sum_w fma(Mw[q,w], tmp[b,p,w,c]) ascending w
__global__ void k_pool_w(int pn, int total /* = B*pn*pn*32 */) {
    int t = blockIdx.x * blockDim.x + threadIdx.x;
    if (t >= total) return;
    int c = t & 31; int n = t >> 5;
    int q = n % pn; int bp = n / pn;        // bp = b*pn + p
    int s = (q*WW)/pn, e = ((q+1)*WW + pn - 1)/pn;
    float ww = 1.0f / (float)(e - s);
    float acc = 0.f;
    for (int w = s; w < e; w++)
        acc = fmaf(ww, g_tmp[(bp*WW + w)*C + c], acc);
    g_z[t] = acc;
}

// ---------------- argmin over codebook (reference-exact fp32 distance) ----------------
// d_j = fl( fl(z2 + esq_j) - 2*dot_j ), dot = single-acc fma chain c ascending.
// Warp lanes = 32 rows; 8 warps/block = 8 code subchunks; grid.y = vocab chunks.
__global__ void k_argmin(const float* __restrict__ emb, int N, int useFrest,
                         int codesPerChunk) {
    __shared__ float s_sc[256];
    __shared__ int   s_id[256];
    const float* zsrc = useFrest ? g_frest : g_z;
    int vec = threadIdx.x & 31;
    int sub = threadIdx.x >> 5;
    int rowv = blockIdx.x * 32 + vec;

    float4 zr[8];
    if (rowv < N) {
        const float4* z4 = (const float4*)(zsrc + (size_t)rowv * C);
        #pragma unroll
        for (int k = 0; k < 8; k++) zr[k] = z4[k];
    } else {
        #pragma unroll
        for (int k = 0; k < 8; k++) zr[k] = make_float4(0.f, 0.f, 0.f, 0.f);
    }

    // z2 = jnp.sum(z*z): rounded squares, sequential ascending adds
    float z2 = 0.f;
    #pragma unroll
    for (int k = 0; k < 8; k++) {
        z2 = __fadd_rn(z2, __fmul_rn(zr[k].x, zr[k].x));
        z2 = __fadd_rn(z2, __fmul_rn(zr[k].y, zr[k].y));
        z2 = __fadd_rn(z2, __fmul_rn(zr[k].z, zr[k].z));
        z2 = __fadd_rn(z2, __fmul_rn(zr[k].w, zr[k].w));
    }

    int cps = codesPerChunk >> 3;
    int j0  = blockIdx.y * codesPerChunk + sub * cps;
    float best = FLT_MAX; int bj = 0;

    for (int j = j0; j < j0 + cps; j += 2) {   // 2 codes in flight for ILP
        const float4* e0 = (const float4*)emb + (size_t)j * 8;
        const float4* e1 = e0 + 8;
        float a0 = 0.f, a1 = 0.f;
        #pragma unroll
        for (int k = 0; k < 8; k++) {
            float4 u = __ldg(e0 + k);
            float4 v = __ldg(e1 + k);
            a0 = fmaf(zr[k].x, u.x, a0); a1 = fmaf(zr[k].x, v.x, a1);
            a0 = fmaf(zr[k].y, u.y, a0); a1 = fmaf(zr[k].y, v.y, a1);
            a0 = fmaf(zr[k].z, u.z, a0); a1 = fmaf(zr[k].z, v.z, a1);
            a0 = fmaf(zr[k].w, u.w, a0); a1 = fmaf(zr[k].w, v.w, a1);
        }
        float t0 = __fadd_rn(z2, __ldg(&g_esq[j]));
        float s0 = __fadd_rn(t0, __fmul_rn(-2.0f, a0));   // *2 exact; one rounded subtract
        float t1 = __fadd_rn(z2, __ldg(&g_esq[j + 1]));
        float s1 = __fadd_rn(t1, __fmul_rn(-2.0f, a1));
        if (s0 < best) { best = s0; bj = j; }             // strict < : first-min tie rule
        if (s1 < best) { best = s1; bj = j + 1; }
    }

    s_sc[threadIdx.x] = best; s_id[threadIdx.x] = bj;
    __syncthreads();
    if (threadIdx.x < 32 && rowv < N) {
        float bb = s_sc[vec]; int bi = s_id[vec];
        #pragma unroll
        for (int s2 = 1; s2 < 8; s2++) {                  // subs ascend in code index
            float cs = s_sc[s2*32 + vec];
            if (cs < bb) { bb = cs; bi = s_id[s2*32 + vec]; }
        }
        g_part[blockIdx.y * N + rowv] = make_float2(bb, __int_as_float(bi));
    }
}

__global__ void k_reduce(int N, int CH) {
    int t = blockIdx.x * blockDim.x + threadIdx.x;
    if (t >= N) return;
    float2 p = g_part[t];
    float bb = p.x; int bi = __float_as_int(p.y);
    for (int c2 = 1; c2 < CH; c2++) {                     // chunks ascend in code index
        float2 q = g_part[c2 * N + t];
        if (q.x < bb) { bb = q.x; bi = __float_as_int(q.y); }
    }
    g_idx[t] = bi;
}

// ---------------- gather + bicubic upsample (H then W) + residual update ----------------
__global__ void k_update(const float* __restrict__ emb, int si, int pn) {
    int t = blockIdx.x * blockDim.x + threadIdx.x;
    if (t >= NELEM) return;
    int c = t & 31; int ow = (t >> 5) & 15; int oh = (t >> 9) & 15; int b = t >> 13;
    int ih0 = g_upi[si][oh], iw0 = g_upi[si][ow];
    float acc = 0.f;
    #pragma unroll
    for (int d = 0; d < 4; d++) {             // W contraction (outer, second stage)
        int iw = iw0 + d;
        if (iw < 0 || iw >= pn) continue;
        float wv = g_upw[si][ow][d];
        float tc = 0.f;
        #pragma unroll
        for (int a = 0; a < 4; a++) {         // H contraction (inner, first stage)
            int ih = ih0 + a;
            if (ih < 0 || ih >= pn) continue;
            float wh = g_upw[si][oh][a];
            int j = g_idx[(b*pn + ih)*pn + iw];
            tc = fmaf(wh, __ldg(&emb[(size_t)j*C + c]), tc);
        }
        acc = fmaf(wv, tc, acc);
    }
    g_fhat[t]  = __fadd_rn(g_fhat[t], acc);
    g_frest[t] = __fadd_rn(g_frest[t], -acc);
}

// ---------------- last scale: gather at full res + transpose to BCHW ----------------
__global__ void k_final(const float* __restrict__ emb, float* __restrict__ out) {
    int t = blockIdx.x * blockDim.x + threadIdx.x;
    if (t >= NELEM) return;
    int c = t & 31; int w = (t >> 5) & 15; int h = (t >> 9) & 15; int b = t >> 13;
    int j = g_idx[(b*HH + h)*WW + w];
    float v = __fadd_rn(g_fhat[t], __ldg(&emb[(size_t)j*C + c]));
    out[((b*C + c)*HH + h)*WW + w] = v;
}

// ---------------- host ----------------
extern "C" void kernel_launch(void* const* d_in, const int* in_sizes, int n_in,
                              void* d_out, int out_size) {
    const float* f   = (const float*)d_in[0];
    const float* emb = (const float*)d_in[1];
    float* out = (float*)d_out;
    static const int PNS[10] = {1,2,3,4,5,6,8,10,13,16};

    k_init_weights<<<1, 256>>>();
    k_esq<<<(VOCAB + 255)/256, 256>>>(emb);
    k_init<<<(NELEM + 255)/256, 256>>>(f);

    for (int si = 0; si < 10; si++) {
        int pn = PNS[si];
        int N  = B * pn * pn;
        int last = (si == 9);

        if (!last) {
            int th = B * pn * 16 * C;
            k_pool_h<<<(th + 255)/256, 256>>>(pn, th);
            int tw = N * C;
            k_pool_w<<<(tw + 255)/256, 256>>>(pn, tw);
        }

        int bx = (N + 31) / 32;
        int CH = 1;
        while (bx * CH < 256 && CH < 16) CH <<= 1;  // keep >= ~256 blocks in flight
        k_argmin<<<dim3(bx, CH), 256>>>(emb, N, last ? 1 : 0, VOCAB / CH);
        k_reduce<<<(N + 255)/256, 256>>>(N, CH);

        if (!last) k_update<<<(NELEM + 255)/256, 256>>>(emb, si, pn);
        else       k_final <<<(NELEM + 255)/256, 256>>>(emb, out);
    }
}

// round 4
// speedup vs baseline: 2.4436x; 2.4436x over previous
#include <cuda_runtime.h>
#include <math.h>
#include <float.h>

#define B 64
#define C 32
#define HH 16
#define WW 16
#define VOCAB 4096
#define NPIX (B*HH*WW)          // 16384
#define NELEM (NPIX*C)          // 524288
typedef unsigned long long ull;

// ---------------- device scratch (static, no allocations) ----------------
__device__ float  g_frest[NELEM];          // residual, BHWC
__device__ float  g_fhat [NELEM];          // accumulator, BHWC
__device__ float  g_z    [64*13*13*32];    // pooled z, largest non-last scale (pn=13)
__device__ float2 g_part [131072];         // partial (score, idx) per (chunk, row)
__device__ int    g_idx  [NPIX];           // argmin indices
__device__ float  g_esq  [VOCAB];          // ||e_j||^2 (reference rounding order)
__device__ float  g_emb2 [VOCAB*C];        // pair-interleaved codebook: [j/2][c][2]
__device__ int    g_upi  [9][16];          // cubic tap start index per (scale, out-pos)
__device__ float  g_upw  [9][16][4];       // cubic tap weights  per (scale, out-pos)

__device__ __constant__ int d_PNS[10] = {1,2,3,4,5,6,8,10,13,16};

// Keys cubic kernel (a = -0.5), matching jax _fill_keys_cubic_kernel, fp32 ops
__device__ __forceinline__ float keys_cubic(float x) {
    if (x >= 2.f) return 0.f;
    if (x >= 1.f) return ((-0.5f*x + 2.5f)*x - 4.f)*x + 2.f;
    return ((1.5f*x - 2.5f)*x)*x + 1.f;
}

// ---------------- setup: esq + interleaved codebook + bicubic tables ----------------
__global__ void k_setup(const float* __restrict__ emb) {
    int t = blockIdx.x * blockDim.x + threadIdx.x;     // 4096 threads
    if (t < VOCAB) {
        float s = 0.f;
        int half = t & 1, pairbase = (t >> 1) * 64;
        #pragma unroll
        for (int c = 0; c < C; c++) {
            float v = emb[(size_t)t * C + c];
            s = __fadd_rn(s, __fmul_rn(v, v));
            g_emb2[pairbase + c * 2 + half] = v;
        }
        g_esq[t] = s;
    }
    if (t < 9 * 16) {
        int si = t >> 4, o = t & 15;
        int pn = d_PNS[si];
        float sf = ((float)o + 0.5f) * ((float)pn / 16.0f) - 0.5f;
        int i0 = (int)floorf(sf) - 1;
        float w[4]; float s = 0.f;
        #pragma unroll
        for (int a = 0; a < 4; a++) {
            int i = i0 + a;
            float wv = 0.f;
            if (i >= 0 && i < pn) wv = keys_cubic(fabsf(sf - (float)i));
            w[a] = wv; s += wv;
        }
        float inv = (fabsf(s) > 1000.f * 1.1920929e-07f) ? 1.f / s : 0.f;
        g_upi[si][o] = i0;
        #pragma unroll
        for (int a = 0; a < 4; a++) g_upw[si][o][a] = w[a] * inv;
    }
}

// ---------------- init: BCHW -> BHWC transpose, f_hat = 0 ----------------
__global__ void k_init(const float* __restrict__ f) {
    int t = blockIdx.x * blockDim.x + threadIdx.x;
    if (t < NELEM) {
        int c = t & 31; int w = (t >> 5) & 15; int h = (t >> 9) & 15; int b = t >> 13;
        g_frest[t] = f[((b*C + c)*HH + h)*WW + w];
        g_fhat[t]  = 0.f;
    }
}

// ---------------- fused area pool (H contraction inner, W outer — einsum order) ----------------
__global__ void k_pool(int pn, int total /* = B*pn*pn*C */) {
    int t = blockIdx.x * blockDim.x + threadIdx.x;
    if (t >= total) return;
    int c = t & 31; int n = t >> 5;
    int q = n % pn; int tmp = n / pn; int p = tmp % pn; int b = tmp / pn;
    int h0 = (p*HH)/pn,  h1 = ((p+1)*HH + pn - 1)/pn;
    int w0 = (q*WW)/pn,  w1 = ((q+1)*WW + pn - 1)/pn;
    float wh = 1.0f / (float)(h1 - h0);
    float ww = 1.0f / (float)(w1 - w0);
    float acc = 0.f;
    for (int w = w0; w < w1; w++) {
        float th = 0.f;
        for (int h = h0; h < h1; h++)
            th = fmaf(wh, g_frest[((b*HH + h)*WW + w)*C + c], th);
        acc = fmaf(ww, th, acc);
    }
    g_z[t] = acc;
}

// ---------------- argmin: smem-tiled codes + packed f32x2 FMA ----------------
// Block = 8 warps = 8 row-groups (256 rows). grid.y splits vocab into chunks.
// Codes streamed through double-buffered smem tiles of 64 codes (pair-interleaved).
// Each fma2 lane is an exact fp32 fma; per-code chain is sequential ascending c
// with a single accumulator -> bit-identical to reference rounding.
__global__ void __launch_bounds__(256, 2) k_argmin(int N, int useFrest, int cpc) {
    __shared__ float s_e[2][2048 + 64];    // per buffer: 32 pairs x 32ch x 2 + 64 esq
    const float* zsrc = useFrest ? g_frest : g_z;
    int lane = threadIdx.x & 31;
    int wid  = threadIdx.x >> 5;
    int row  = blockIdx.x * 256 + wid * 32 + lane;

    // load z row, compute z2 (reference order), pack (z_c, z_c)
    float zf[C];
    if (row < N) {
        const float4* z4 = (const float4*)(zsrc + (size_t)row * C);
        #pragma unroll
        for (int k = 0; k < 8; k++) {
            float4 v = z4[k];
            zf[4*k] = v.x; zf[4*k+1] = v.y; zf[4*k+2] = v.z; zf[4*k+3] = v.w;
        }
    } else {
        #pragma unroll
        for (int k = 0; k < C; k++) zf[k] = 0.f;
    }
    float z2 = 0.f;
    #pragma unroll
    for (int k = 0; k < C; k++) z2 = __fadd_rn(z2, __fmul_rn(zf[k], zf[k]));
    ull zz[C];
    #pragma unroll
    for (int k = 0; k < C; k++)
        asm("mov.b64 %0, {%1, %2};" : "=l"(zz[k]) : "f"(zf[k]), "f"(zf[k]));

    int code0 = blockIdx.y * cpc;
    int T = cpc >> 6;                       // tiles of 64 codes
    float best = FLT_MAX; int bj = 0;

    // prime tile 0
    {
        const float4* src = (const float4*)(g_emb2 + (size_t)code0 * C);
        float4* dst = (float4*)s_e[0];
        dst[threadIdx.x]       = src[threadIdx.x];
        dst[256 + threadIdx.x] = src[256 + threadIdx.x];
        if (threadIdx.x < 16)
            ((float4*)(s_e[0] + 2048))[threadIdx.x] =
                ((const float4*)(g_esq + code0))[threadIdx.x];
    }

    for (int t = 0; t < T; t++) {
        __syncthreads();
        if (t + 1 < T) {
            int cb = code0 + (t + 1) * 64;
            const float4* src = (const float4*)(g_emb2 + (size_t)cb * C);
            float4* dst = (float4*)s_e[(t + 1) & 1];
            dst[threadIdx.x]       = src[threadIdx.x];
            dst[256 + threadIdx.x] = src[256 + threadIdx.x];
            if (threadIdx.x < 16)
                ((float4*)(s_e[(t + 1) & 1] + 2048))[threadIdx.x] =
                    ((const float4*)(g_esq + cb))[threadIdx.x];
        }
        int bsel = t & 1;
        unsigned sbase = (unsigned)__cvta_generic_to_shared(s_e[bsel]);
        const float* se = s_e[bsel] + 2048;
        #pragma unroll 1
        for (int p = 0; p < 32; p += 2) {   // 2 code-pairs (4 codes) in flight
            ull acc0 = 0ULL, acc1 = 0ULL;   // (+0,+0) packed
            unsigned a0 = sbase + (unsigned)p * 256u;
            unsigned a1 = a0 + 256u;
            #pragma unroll
            for (int c = 0; c < C; c += 2) {
                ull u0, u1, v0, v1;
                asm volatile("ld.shared.v2.b64 {%0,%1}, [%2];"
                             : "=l"(u0), "=l"(u1) : "r"(a0 + (unsigned)c * 8u));
                asm volatile("ld.shared.v2.b64 {%0,%1}, [%2];"
                             : "=l"(v0), "=l"(v1) : "r"(a1 + (unsigned)c * 8u));
                asm("fma.rn.f32x2 %0, %1, %2, %0;" : "+l"(acc0) : "l"(zz[c]),   "l"(u0));
                asm("fma.rn.f32x2 %0, %1, %2, %0;" : "+l"(acc1) : "l"(zz[c]),   "l"(v0));
                asm("fma.rn.f32x2 %0, %1, %2, %0;" : "+l"(acc0) : "l"(zz[c+1]), "l"(u1));
                asm("fma.rn.f32x2 %0, %1, %2, %0;" : "+l"(acc1) : "l"(zz[c+1]), "l"(v1));
            }
            float lo0, hi0, lo1, hi1;
            asm("mov.b64 {%0,%1}, %2;" : "=f"(lo0), "=f"(hi0) : "l"(acc0));
            asm("mov.b64 {%0,%1}, %2;" : "=f"(lo1), "=f"(hi1) : "l"(acc1));
            // d = fl( fl(z2 + esq) - 2*dot )
            float s0 = __fadd_rn(__fadd_rn(z2, se[2*p + 0]), __fmul_rn(-2.f, lo0));
            float s1 = __fadd_rn(__fadd_rn(z2, se[2*p + 1]), __fmul_rn(-2.f, hi0));
            float s2 = __fadd_rn(__fadd_rn(z2, se[2*p + 2]), __fmul_rn(-2.f, lo1));
            float s3 = __fadd_rn(__fadd_rn(z2, se[2*p + 3]), __fmul_rn(-2.f, hi1));
            int j = code0 + t * 64 + 2 * p;
            if (s0 < best) { best = s0; bj = j;     }   // strict < : first-min tie rule
            if (s1 < best) { best = s1; bj = j + 1; }
            if (s2 < best) { best = s2; bj = j + 2; }
            if (s3 < best) { best = s3; bj = j + 3; }
        }
    }
    if (row < N) g_part[blockIdx.y * N + row] = make_float2(best, __int_as_float(bj));
}

__global__ void k_reduce(int N, int CH) {
    int t = blockIdx.x * blockDim.x + threadIdx.x;
    if (t >= N) return;
    float2 p = g_part[t];
    float bb = p.x; int bi = __float_as_int(p.y);
    for (int c2 = 1; c2 < CH; c2++) {                 // chunks ascend in code index
        float2 q = g_part[c2 * N + t];
        if (q.x < bb) { bb = q.x; bi = __float_as_int(q.y); }
    }
    g_idx[t] = bi;
}

// ---------------- gather + bicubic upsample (H then W) + residual update ----------------
__global__ void k_update(const float* __restrict__ emb, int si, int pn) {
    int t = blockIdx.x * blockDim.x + threadIdx.x;
    if (t >= NELEM) return;
    int c = t & 31; int ow = (t >> 5) & 15; int oh = (t >> 9) & 15; int b = t >> 13;
    int ih0 = g_upi[si][oh], iw0 = g_upi[si][ow];
    float acc = 0.f;
    #pragma unroll
    for (int d = 0; d < 4; d++) {             // W contraction (outer, second stage)
        int iw = iw0 + d;
        if (iw < 0 || iw >= pn) continue;
        float wv = g_upw[si][ow][d];
        float tc = 0.f;
        #pragma unroll
        for (int a = 0; a < 4; a++) {         // H contraction (inner, first stage)
            int ih = ih0 + a;
            if (ih < 0 || ih >= pn) continue;
            float wh = g_upw[si][oh][a];
            int j = g_idx[(b*pn + ih)*pn + iw];
            tc = fmaf(wh, __ldg(&emb[(size_t)j*C + c]), tc);
        }
        acc = fmaf(wv, tc, acc);
    }
    g_fhat[t]  = __fadd_rn(g_fhat[t], acc);
    g_frest[t] = __fadd_rn(g_frest[t], -acc);
}

// ---------------- last scale: gather at full res + transpose to BCHW ----------------
__global__ void k_final(const float* __restrict__ emb, float* __restrict__ out) {
    int t = blockIdx.x * blockDim.x + threadIdx.x;
    if (t >= NELEM) return;
    int c = t & 31; int w = (t >> 5) & 15; int h = (t >> 9) & 15; int b = t >> 13;
    int j = g_idx[(b*HH + h)*WW + w];
    float v = __fadd_rn(g_fhat[t], __ldg(&emb[(size_t)j*C + c]));
    out[((b*C + c)*HH + h)*WW + w] = v;
}

// ---------------- host ----------------
extern "C" void kernel_launch(void* const* d_in, const int* in_sizes, int n_in,
                              void* d_out, int out_size) {
    const float* f   = (const float*)d_in[0];
    const float* emb = (const float*)d_in[1];
    float* out = (float*)d_out;
    static const int PNS[10] = {1,2,3,4,5,6,8,10,13,16};
    static const int CHS[10] = {64,64,64,64,32,32,16,16,8,8};  // vocab chunks per scale

    k_setup<<<(VOCAB + 255)/256, 256>>>(emb);
    k_init<<<(NELEM + 255)/256, 256>>>(f);

    for (int si = 0; si < 10; si++) {
        int pn = PNS[si];
        int N  = B * pn * pn;
        int last = (si == 9);

        if (!last) {
            int tw = N * C;
            k_pool<<<(tw + 255)/256, 256>>>(pn, tw);
        }

        int bx = (N + 255) / 256;
        int CH = CHS[si];
        k_argmin<<<dim3(bx, CH), 256>>>(N, last ? 1 : 0, VOCAB / CH);
        k_reduce<<<(N + 255)/256, 256>>>(N, CH);

        if (!last) k_update<<<(NELEM + 255)/256, 256>>>(emb, si, pn);
        else       k_final <<<(NELEM + 255)/256, 256>>>(emb, out);
    }
}

// round 6
// speedup vs baseline: 2.8314x; 1.1587x over previous
#include <cuda_runtime.h>
#include <math.h>
#include <float.h>

#define B 64
#define C 32
#define HH 16
#define WW 16
#define VOCAB 4096
#define NPIX (B*HH*WW)          // 16384
#define NELEM (NPIX*C)          // 524288
#define NROWS_TOT 43520         // sum of N over all 10 scales
typedef unsigned long long ull;

// ---------------- device scratch (static, no allocations) ----------------
__device__ float  g_frest[NELEM];          // residual, BHWC
__device__ float  g_fhat [NELEM];          // accumulator, BHWC
__device__ float  g_z    [64*13*13*32];    // pooled z, largest non-last scale (pn=13)
__device__ ull    g_best [NROWS_TOT];      // packed (ordered-score<<32)|idx per row, all scales
__device__ float  g_esq  [VOCAB];          // ||e_j||^2 (reference rounding order)
__device__ float  g_emb2 [VOCAB*C];        // pair-interleaved codebook: [j/2][c][2]
__device__ int    g_upi  [9][16];          // cubic tap start index per (scale, out-pos)
__device__ float  g_upw  [9][16][4];       // cubic tap weights  per (scale, out-pos)

__device__ __constant__ int d_PNS[10] = {1,2,3,4,5,6,8,10,13,16};

// Keys cubic kernel (a = -0.5), matching jax _fill_keys_cubic_kernel, fp32 ops
__device__ __forceinline__ float keys_cubic(float x) {
    if (x >= 2.f) return 0.f;
    if (x >= 1.f) return ((-0.5f*x + 2.5f)*x - 4.f)*x + 2.f;
    return ((1.5f*x - 2.5f)*x)*x + 1.f;
}

// ---------------- init: transpose + fhat=0 + g_best=~0 + esq + emb2 + cubic tables ----------
__global__ void k_init(const float* __restrict__ f, const float* __restrict__ emb) {
    int t = blockIdx.x * blockDim.x + threadIdx.x;      // 131072 threads
    // BCHW -> BHWC transpose (4 channels per thread), f_hat = 0
    {
        int c4 = t & 7; int w = (t >> 3) & 15; int h = (t >> 7) & 15; int b = t >> 11;
        int c = c4 * 4;
        const float* fp = f + ((size_t)b*C + c)*256 + h*WW + w;   // stride 256 per channel
        float4 v = make_float4(fp[0], fp[256], fp[512], fp[768]);
        ((float4*)g_frest)[t] = v;
        ((float4*)g_fhat)[t]  = make_float4(0.f, 0.f, 0.f, 0.f);
    }
    if (t < NROWS_TOT) g_best[t] = ~0ULL;
    if (t < VOCAB) {
        float s = 0.f;
        int half = t & 1, pairbase = (t >> 1) * 64;
        #pragma unroll
        for (int c = 0; c < C; c++) {
            float v = emb[(size_t)t * C + c];
            s = __fadd_rn(s, __fmul_rn(v, v));
            g_emb2[pairbase + c * 2 + half] = v;
        }
        g_esq[t] = s;
    }
    if (t < 9 * 16) {
        int si = t >> 4, o = t & 15;
        int pn = d_PNS[si];
        float sf = ((float)o + 0.5f) * ((float)pn / 16.0f) - 0.5f;
        int i0 = (int)floorf(sf) - 1;
        float w[4]; float s = 0.f;
        #pragma unroll
        for (int a = 0; a < 4; a++) {
            int i = i0 + a;
            float wv = 0.f;
            if (i >= 0 && i < pn) wv = keys_cubic(fabsf(sf - (float)i));
            w[a] = wv; s += wv;
        }
        float inv = (fabsf(s) > 1000.f * 1.1920929e-07f) ? 1.f / s : 0.f;
        g_upi[si][o] = i0;
        #pragma unroll
        for (int a = 0; a < 4; a++) g_upw[si][o][a] = w[a] * inv;
    }
}

// ---------------- fused area pool, float4 channels (H inner, W outer — einsum order) -----
__global__ void k_pool(int pn, int total /* = N*8 */) {
    int t = blockIdx.x * blockDim.x + threadIdx.x;
    if (t >= total) return;
    int c4 = t & 7; int n = t >> 3;
    int q = n % pn; int tmp = n / pn; int p = tmp % pn; int b = tmp / pn;
    int h0 = (p*HH)/pn,  h1 = ((p+1)*HH + pn - 1)/pn;
    int w0 = (q*WW)/pn,  w1 = ((q+1)*WW + pn - 1)/pn;
    float wh = 1.0f / (float)(h1 - h0);
    float ww = 1.0f / (float)(w1 - w0);
    float4 acc = make_float4(0.f,0.f,0.f,0.f);
    for (int w = w0; w < w1; w++) {
        float4 th = make_float4(0.f,0.f,0.f,0.f);
        for (int h = h0; h < h1; h++) {
            float4 v = ((const float4*)g_frest)[((b*HH + h)*WW + w)*8 + c4];
            th.x = fmaf(wh, v.x, th.x); th.y = fmaf(wh, v.y, th.y);
            th.z = fmaf(wh, v.z, th.z); th.w = fmaf(wh, v.w, th.w);
        }
        acc.x = fmaf(ww, th.x, acc.x); acc.y = fmaf(ww, th.y, acc.y);
        acc.z = fmaf(ww, th.z, acc.z); acc.w = fmaf(ww, th.w, acc.w);
    }
    ((float4*)g_z)[t] = acc;
}

// ---------------- argmin: smem-tiled codes, packed f32x2 FMA, 4 chains, atomic reduce ----
// Block = 8 warps = 256 rows; grid.y = vocab chunks. Per-code chain is a single
// sequential fp32 fma chain ascending c (each f32x2 lane is exact fp32) ->
// bit-identical to reference rounding. Cross-chunk reduction via atomicMin on
// key=(ordered_score<<32)|idx, which reproduces jnp.argmin's first-min tie rule.
__global__ void __launch_bounds__(256, 2) k_argmin(int N, int useFrest, int cpc,
                                                   int sliceBase) {
    __shared__ float s_e[2][2048 + 64];    // per buffer: 32 pairs x 32ch x 2 + 64 esq
    const float* zsrc = useFrest ? g_frest : g_z;
    int lane = threadIdx.x & 31;
    int wid  = threadIdx.x >> 5;
    int row  = blockIdx.x * 256 + wid * 32 + lane;

    float zf[C];
    if (row < N) {
        const float4* z4 = (const float4*)(zsrc + (size_t)row * C);
        #pragma unroll
        for (int k = 0; k < 8; k++) {
            float4 v = z4[k];
            zf[4*k] = v.x; zf[4*k+1] = v.y; zf[4*k+2] = v.z; zf[4*k+3] = v.w;
        }
    } else {
        #pragma unroll
        for (int k = 0; k < C; k++) zf[k] = 0.f;
    }
    float z2 = 0.f;
    #pragma unroll
    for (int k = 0; k < C; k++) z2 = __fadd_rn(z2, __fmul_rn(zf[k], zf[k]));
    ull zz[C];
    #pragma unroll
    for (int k = 0; k < C; k++)
        asm("mov.b64 %0, {%1, %2};" : "=l"(zz[k]) : "f"(zf[k]), "f"(zf[k]));

    int code0 = blockIdx.y * cpc;
    int T = cpc >> 6;                       // tiles of 64 codes
    float best = FLT_MAX; int bj = 0;

    {   // prime tile 0
        const float4* src = (const float4*)(g_emb2 + (size_t)code0 * C);
        float4* dst = (float4*)s_e[0];
        dst[threadIdx.x]       = src[threadIdx.x];
        dst[256 + threadIdx.x] = src[256 + threadIdx.x];
        if (threadIdx.x < 16)
            ((float4*)(s_e[0] + 2048))[threadIdx.x] =
                ((const float4*)(g_esq + code0))[threadIdx.x];
    }

    for (int t = 0; t < T; t++) {
        __syncthreads();
        if (t + 1 < T) {
            int cb = code0 + (t + 1) * 64;
            const float4* src = (const float4*)(g_emb2 + (size_t)cb * C);
            float4* dst = (float4*)s_e[(t + 1) & 1];
            dst[threadIdx.x]       = src[threadIdx.x];
            dst[256 + threadIdx.x] = src[256 + threadIdx.x];
            if (threadIdx.x < 16)
                ((float4*)(s_e[(t + 1) & 1] + 2048))[threadIdx.x] =
                    ((const float4*)(g_esq + cb))[threadIdx.x];
        }
        int bsel = t & 1;
        unsigned sbase = (unsigned)__cvta_generic_to_shared(s_e[bsel]);
        const float* se = s_e[bsel] + 2048;
        #pragma unroll 1
        for (int p = 0; p < 32; p += 4) {   // 4 code-pairs (8 codes) in flight
            ull acc[4]; acc[0]=0ULL; acc[1]=0ULL; acc[2]=0ULL; acc[3]=0ULL;
            unsigned ab = sbase + (unsigned)p * 256u;
            #pragma unroll
            for (int c = 0; c < C; c += 2) {
                ull u0[4], u1[4];
                #pragma unroll
                for (int i = 0; i < 4; i++)
                    asm volatile("ld.shared.v2.b64 {%0,%1}, [%2];"
                                 : "=l"(u0[i]), "=l"(u1[i])
                                 : "r"(ab + (unsigned)i * 256u + (unsigned)c * 8u));
                #pragma unroll
                for (int i = 0; i < 4; i++)   // same-chain FMAs 4 instrs apart
                    asm("fma.rn.f32x2 %0, %1, %2, %0;" : "+l"(acc[i]) : "l"(zz[c]),   "l"(u0[i]));
                #pragma unroll
                for (int i = 0; i < 4; i++)
                    asm("fma.rn.f32x2 %0, %1, %2, %0;" : "+l"(acc[i]) : "l"(zz[c+1]), "l"(u1[i]));
            }
            int jb = code0 + t * 64 + 2 * p;
            #pragma unroll
            for (int i = 0; i < 4; i++) {
                float lo, hi;
                asm("mov.b64 {%0,%1}, %2;" : "=f"(lo), "=f"(hi) : "l"(acc[i]));
                // d = fl( fl(z2 + esq) - 2*dot )
                float s0 = __fadd_rn(__fadd_rn(z2, se[2*p + 2*i    ]), __fmul_rn(-2.f, lo));
                float s1 = __fadd_rn(__fadd_rn(z2, se[2*p + 2*i + 1]), __fmul_rn(-2.f, hi));
                if (s0 < best) { best = s0; bj = jb + 2*i;     }   // strict <
                if (s1 < best) { best = s1; bj = jb + 2*i + 1; }
            }
        }
    }
    if (row < N) {
        unsigned sb = __float_as_uint(best);
        sb = (sb & 0x80000000u) ? ~sb : (sb | 0x80000000u);      // monotone float->uint
        ull key = ((ull)sb << 32) | (unsigned)bj;
        atomicMin(&g_best[sliceBase + row], key);
    }
}

// ---------------- gather + bicubic upsample (H then W) + residual update, float4 ---------
__global__ void k_update(const float* __restrict__ emb, int si, int pn, int base) {
    int t = blockIdx.x * blockDim.x + threadIdx.x;     // 131072 threads
    if (t >= NPIX * 8) return;
    int c4 = t & 7; int ow = (t >> 3) & 15; int oh = (t >> 7) & 15; int b = t >> 11;
    int ih0 = g_upi[si][oh], iw0 = g_upi[si][ow];
    float4 acc = make_float4(0.f,0.f,0.f,0.f);
    #pragma unroll
    for (int d = 0; d < 4; d++) {             // W contraction (outer, second stage)
        int iw = iw0 + d;
        if (iw < 0 || iw >= pn) continue;
        float wv = g_upw[si][ow][d];
        float4 tc = make_float4(0.f,0.f,0.f,0.f);
        #pragma unroll
        for (int a = 0; a < 4; a++) {         // H contraction (inner, first stage)
            int ih = ih0 + a;
            if (ih < 0 || ih >= pn) continue;
            float wh = g_upw[si][oh][a];
            int j = (int)(unsigned)g_best[base + (b*pn + ih)*pn + iw];
            float4 e = __ldg((const float4*)emb + (size_t)j * 8 + c4);
            tc.x = fmaf(wh, e.x, tc.x); tc.y = fmaf(wh, e.y, tc.y);
            tc.z = fmaf(wh, e.z, tc.z); tc.w = fmaf(wh, e.w, tc.w);
        }
        acc.x = fmaf(wv, tc.x, acc.x); acc.y = fmaf(wv, tc.y, acc.y);
        acc.z = fmaf(wv, tc.z, acc.z); acc.w = fmaf(wv, tc.w, acc.w);
    }
    float4 fh = ((float4*)g_fhat)[t];
    float4 fr = ((float4*)g_frest)[t];
    fh.x = __fadd_rn(fh.x, acc.x); fh.y = __fadd_rn(fh.y, acc.y);
    fh.z = __fadd_rn(fh.z, acc.z); fh.w = __fadd_rn(fh.w, acc.w);
    fr.x = __fadd_rn(fr.x, -acc.x); fr.y = __fadd_rn(fr.y, -acc.y);
    fr.z = __fadd_rn(fr.z, -acc.z); fr.w = __fadd_rn(fr.w, -acc.w);
    ((float4*)g_fhat)[t]  = fh;
    ((float4*)g_frest)[t] = fr;
}

// ---------------- last scale: gather at full res + transpose to BCHW ----------------
__global__ void k_final(const float* __restrict__ emb, float* __restrict__ out, int base) {
    int t = blockIdx.x * blockDim.x + threadIdx.x;     // 131072 threads
    if (t >= NPIX * 8) return;
    int c4 = t & 7; int w = (t >> 3) & 15; int h = (t >> 7) & 15; int b = t >> 11;
    int j = (int)(unsigned)g_best[base + (b*HH + h)*WW + w];
    float4 fh = ((float4*)g_fhat)[t];
    float4 e  = __ldg((const float4*)emb + (size_t)j * 8 + c4);
    int c = c4 * 4;
    float* op = out + ((size_t)b*C + c)*256 + h*WW + w;
    op[0]   = __fadd_rn(fh.x, e.x);
    op[256] = __fadd_rn(fh.y, e.y);
    op[512] = __fadd_rn(fh.z, e.z);
    op[768] = __fadd_rn(fh.w, e.w);
}

// ---------------- host ----------------
extern "C" void kernel_launch(void* const* d_in, const int* in_sizes, int n_in,
                              void* d_out, int out_size) {
    const float* f   = (const float*)d_in[0];
    const float* emb = (const float*)d_in[1];
    float* out = (float*)d_out;
    static const int PNS [10] = {1,2,3,4,5,6,8,10,13,16};
    static const int CHS [10] = {64,64,64,64,32,32,16,16,8,8};   // vocab chunks per scale
    static const int BASE[10] = {0,64,320,896,1920,3520,5824,9920,16320,27136};

    k_init<<<512, 256>>>(f, emb);

    for (int si = 0; si < 10; si++) {
        int pn = PNS[si];
        int N  = B * pn * pn;
        int last = (si == 9);

        if (!last) {
            int tw = N * 8;
            k_pool<<<(tw + 255)/256, 256>>>(pn, tw);
        }

        int bx = (N + 255) / 256;
        int CH = CHS[si];
        k_argmin<<<dim3(bx, CH), 256>>>(N, last ? 1 : 0, VOCAB / CH, BASE[si]);

        if (!last) k_update<<<512, 256>>>(emb, si, pn, BASE[si]);
        else       k_final <<<512, 256>>>(emb, out, BASE[si]);
    }
}